// round 10
// baseline (speedup 1.0000x reference)
#include <cuda_runtime.h>
#include <cuda_fp16.h>
#include <stdint.h>
#include <math.h>

// ---------------- problem constants ----------------
#define DT   1024
#define FT   4096
#define ET   8
#define TT   8192
#define KSEL 2

#define BM    128
#define SLOTS 17408
#define MAXT  136
#define BK    64

// ---- unified staging: A 16K | B 16K per stage, 3 stages ----
#define STG      32768
#define OFF_A    0
#define OFF_B    16384
#define SMEM_SZ  98304

// A swizzle: 16B chunk c (0..7) within 128B row r
#define SWZ(r, c) ((uint32_t)((((c) ^ ((r) & 7))) << 4))
// B swizzle: [K][N] rows of 256B (128 n x 2B)
#define BSWZ(k, n) ((uint32_t)((k) * 256 + (((((n) >> 3) ^ ((k) & 7))) << 4) + (((n) & 7) * 2)))

// ---------------- device scratch ----------------
__device__ unsigned short g_xtok[(size_t)TT * DT];     // fp16 x, token order
__device__ unsigned short g_hh[(size_t)SLOTS * FT];    // fp16 h
__device__ float g_cbuf[(size_t)2 * TT * DT];          // per-assignment-rank output

__device__ int   g_perm[SLOTS];
__device__ float g_pw[SLOTS];
__device__ unsigned char g_pk[SLOTS];                  // assignment rank (0/1)
__device__ int   g_topk_e[TT * KSEL];
__device__ float g_topk_w[TT * KSEL];
__device__ int   g_counts[ET];
__device__ int   g_tile_e[MAXT];
__device__ int   g_tile_r0[MAXT];
__device__ int   g_ntiles;
__device__ int   g_work1;
__device__ int   g_work2;

// ---------------- helpers ----------------
__device__ __forceinline__ uint32_t s2u(const void* p) {
    uint32_t a;
    asm("{ .reg .u64 t; cvta.to.shared.u64 t, %1; cvt.u32.u64 %0, t; }" : "=r"(a) : "l"(p));
    return a;
}
__device__ __forceinline__ void cpasync16(uint32_t dst, const void* src) {
    asm volatile("cp.async.cg.shared.global [%0], [%1], 16;" :: "r"(dst), "l"(src));
}
#define CP_COMMIT() asm volatile("cp.async.commit_group;" ::: "memory")
#define CP_WAIT1()  asm volatile("cp.async.wait_group 1;" ::: "memory")
#define CP_WAIT0()  asm volatile("cp.async.wait_group 0;" ::: "memory")

__device__ __forceinline__ void ldsm4(uint32_t* r, uint32_t a) {
    asm volatile("ldmatrix.sync.aligned.m8n8.x4.shared.b16 {%0,%1,%2,%3}, [%4];"
                 : "=r"(r[0]), "=r"(r[1]), "=r"(r[2]), "=r"(r[3]) : "r"(a));
}
__device__ __forceinline__ void ldsm4t(uint32_t* r, uint32_t a) {
    asm volatile("ldmatrix.sync.aligned.m8n8.x4.trans.shared.b16 {%0,%1,%2,%3}, [%4];"
                 : "=r"(r[0]), "=r"(r[1]), "=r"(r[2]), "=r"(r[3]) : "r"(a));
}
__device__ __forceinline__ void mma16816(float* c, const uint32_t* a, const uint32_t* b) {
    asm volatile("mma.sync.aligned.m16n8k16.row.col.f32.f16.f16.f32 "
                 "{%0,%1,%2,%3}, {%4,%5,%6,%7}, {%8,%9}, {%0,%1,%2,%3};"
                 : "+f"(c[0]), "+f"(c[1]), "+f"(c[2]), "+f"(c[3])
                 : "r"(a[0]), "r"(a[1]), "r"(a[2]), "r"(a[3]), "r"(b[0]), "r"(b[1]));
}
__device__ __forceinline__ void sts64(uint32_t a, uint32_t x, uint32_t y) {
    asm volatile("st.shared.v2.b32 [%0], {%1,%2};" :: "r"(a), "r"(x), "r"(y) : "memory");
}
__device__ __forceinline__ uint32_t packh2(float f0, float f1) {
    uint32_t d;
    asm("cvt.rn.f16x2.f32 %0, %1, %2;" : "=r"(d) : "f"(f1), "f"(f0));
    return d;
}

// ---------------- launch 1: init (counts + work counters) ----------------
__global__ void init_kernel() {
    int i = threadIdx.x;
    if (i < ET) g_counts[i] = 0;
    if (i == 8) g_work1 = 0;
    if (i == 9) g_work2 = 0;
}

// ---------------- launch 2: gating + fp16 conversion of x ----------------
__global__ void gate_conv_kernel(const float* __restrict__ x, const float* __restrict__ gw) {
    int gwarp = (blockIdx.x * blockDim.x + threadIdx.x) >> 5;
    int lane = threadIdx.x & 31;
    if (gwarp >= TT) return;
    const float* xr = x + (size_t)gwarp * DT;
    float acc[ET];
#pragma unroll
    for (int e = 0; e < ET; e++) acc[e] = 0.f;
    for (int i = lane; i < DT; i += 32) {
        float xv = xr[i];
        const float* g = gw + (size_t)i * ET;
#pragma unroll
        for (int e = 0; e < ET; e++) acc[e] += xv * g[e];
    }
    // convert this token's row to fp16 (row is hot in L1)
    {
        const float4* xr4 = (const float4*)xr;
        uint2* dst = (uint2*)(g_xtok + (size_t)gwarp * DT);
#pragma unroll
        for (int i = lane; i < DT / 4; i += 32) {
            float4 v = xr4[i];
            dst[i] = make_uint2(packh2(v.x, v.y), packh2(v.z, v.w));
        }
    }
#pragma unroll
    for (int e = 0; e < ET; e++)
#pragma unroll
        for (int o = 16; o; o >>= 1)
            acc[e] += __shfl_xor_sync(0xFFFFFFFFu, acc[e], o);
    if (lane == 0) {
        int i0 = 0; float v0 = acc[0];
#pragma unroll
        for (int e = 1; e < ET; e++) if (acc[e] > v0) { v0 = acc[e]; i0 = e; }
        int i1 = -1; float v1 = -3.4e38f;
#pragma unroll
        for (int e = 0; e < ET; e++) if (e != i0 && acc[e] > v1) { v1 = acc[e]; i1 = e; }
        float e1 = expf(v1 - v0);
        float inv = 1.0f / (1.0f + e1);
        int b = gwarp * KSEL;
        g_topk_e[b] = i0;     g_topk_w[b] = inv;
        g_topk_e[b + 1] = i1; g_topk_w[b + 1] = e1 * inv;
        atomicAdd(&g_counts[i0], 1);
        atomicAdd(&g_counts[i1], 1);
    }
}

// ---------------- launch 3: plan + perm init + scatter (single block) ----------------
__global__ void plan_scatter_kernel() {
    __shared__ int s_padoff[ET];
    __shared__ int s_cur[ET];
    int tid = threadIdx.x;
    // init perm
    for (int i = tid; i < SLOTS; i += 256) g_perm[i] = -1;
    if (tid == 0) {
        int off = 0, tile = 0;
        for (int e = 0; e < ET; e++) {
            s_padoff[e] = off;
            int c = g_counts[e];
            int nt = (c + BM - 1) / BM;
            for (int t = 0; t < nt; t++) {
                g_tile_e[tile] = e;
                g_tile_r0[tile] = off + t * BM;
                tile++;
            }
            off += nt * BM;
        }
        g_ntiles = tile;
    }
    if (tid < ET) s_cur[tid] = 0;
    __syncthreads();
    for (int a = tid; a < TT * KSEL; a += 256) {
        int e = g_topk_e[a];
        int pos = atomicAdd(&s_cur[e], 1);
        int slot = s_padoff[e] + pos;
        g_perm[slot] = a >> 1;
        g_pw[slot] = g_topk_w[a];
        g_pk[slot] = (unsigned char)(a & 1);
    }
}

// ---------------- shared GEMM machinery ----------------
#define ISSUE_A(s, KS) do {                                              \
    if ((s) < (KS)) {                                                    \
        uint32_t bb = sb + ((s) % 3) * STG;                              \
        size_t ko = (size_t)(s) * 128;                                   \
        _Pragma("unroll")                                                \
        for (int j = 0; j < 4; j++) cpasync16(bb + dstA[j], srcA[j] + ko); \
    }                                                                    \
    CP_COMMIT();                                                         \
} while (0)

#define LDG_B(s) do {                                                    \
    _Pragma("unroll")                                                    \
    for (int j = 0; j < 8; j++) {                                        \
        float4 v = *(const float4*)(srcB0 + (size_t)j * bstride          \
                                    + (size_t)(s) * 64 * bstride);       \
        bp[2 * j]     = packh2(v.x, v.y);                                \
        bp[2 * j + 1] = packh2(v.z, v.w);                                \
    }                                                                    \
} while (0)

#define STS_B(s) do {                                                    \
    uint32_t bb = sb + ((s) % 3) * STG;                                  \
    _Pragma("unroll")                                                    \
    for (int j = 0; j < 8; j++)                                          \
        sts64(bb + OFF_B + BSWZ(wid * 8 + j, bn), bp[2 * j], bp[2 * j + 1]); \
} while (0)

#define GEMM_MAINLOOP(KS) do {                                           \
    ISSUE_A(0, KS);                                                      \
    ISSUE_A(1, KS);                                                      \
    LDG_B(0);                                                            \
    for (int s = 0; s < (KS); s++) {                                     \
        CP_WAIT1();                                                      \
        STS_B(s);                                                        \
        __syncthreads();                                                 \
        if (s + 1 < (KS)) LDG_B(s + 1);                                  \
        ISSUE_A(s + 2, KS);                                              \
        uint32_t b = sb + (s % 3) * STG;                                 \
        _Pragma("unroll")                                                \
        for (int ks = 0; ks < 4; ks++) {                                 \
            uint32_t ah[4][4], bhf[4][2];                                \
            int rr = lane & 15;                                          \
            int ch = 2 * ks + (lane >> 4);                               \
            _Pragma("unroll")                                            \
            for (int mf = 0; mf < 4; mf++) {                             \
                int r = wm * 64 + mf * 16 + rr;                          \
                ldsm4(ah[mf], b + OFF_A + r * 128 + SWZ(r, ch));         \
            }                                                            \
            {                                                            \
                int mat = lane >> 3, li = lane & 7;                      \
                int kk = ks * 16 + ((mat & 1) << 3) + li;                \
                _Pragma("unroll")                                        \
                for (int bi = 0; bi < 2; bi++) {                         \
                    int nn = wn * 32 + bi * 16 + ((mat >> 1) << 3);      \
                    uint32_t t4[4];                                      \
                    ldsm4t(t4, b + OFF_B + BSWZ(kk, nn));                \
                    bhf[bi*2+0][0] = t4[0]; bhf[bi*2+0][1] = t4[1];      \
                    bhf[bi*2+1][0] = t4[2]; bhf[bi*2+1][1] = t4[3];      \
                }                                                        \
            }                                                            \
            _Pragma("unroll")                                            \
            for (int mf = 0; mf < 4; mf++)                               \
                _Pragma("unroll")                                        \
                for (int nf = 0; nf < 4; nf++)                           \
                    mma16816(cf[mf][nf], ah[mf], bhf[nf]);               \
        }                                                                \
    }                                                                    \
    CP_WAIT0();                                                          \
    __syncthreads();                                                     \
} while (0)

#define STORE_C_SMEM() do {                                              \
    float* Cs = (float*)dynsm;                                           \
    int g = lane >> 2, t4i = lane & 3;                                   \
    _Pragma("unroll")                                                    \
    for (int mf = 0; mf < 4; mf++)                                       \
        _Pragma("unroll")                                                \
        for (int nf = 0; nf < 4; nf++) {                                 \
            int m0 = wm * 64 + mf * 16 + g;                              \
            int n0 = wn * 32 + nf * 8 + 2 * t4i;                         \
            Cs[m0 * 132 + n0]           = cf[mf][nf][0];                 \
            Cs[m0 * 132 + n0 + 1]       = cf[mf][nf][1];                 \
            Cs[(m0 + 8) * 132 + n0]     = cf[mf][nf][2];                 \
            Cs[(m0 + 8) * 132 + n0 + 1] = cf[mf][nf][3];                 \
        }                                                                \
} while (0)

// ---------------- launch 4: GEMM1 (persistent) — PROFILED SLOT ----------------
__global__ __launch_bounds__(256, 2) void gemm1_kernel(
        const float* __restrict__ wi0, const float* __restrict__ wi1) {
    extern __shared__ char dynsm[];
    __shared__ int s_item;
    int nt = g_ntiles;
    int total = nt * 64;
    int tid = threadIdx.x;
    int lane = tid & 31;
    int wid = tid >> 5;
    int wm = wid >> 2, wn = wid & 3;
    uint32_t sb = s2u(dynsm);

    uint32_t dstA[4];
    int arow[4], acol[4];
#pragma unroll
    for (int j = 0; j < 4; j++) {
        int id = tid + j * 256;
        arow[j] = (id >> 3) & 127;
        acol[j] = id & 7;
        dstA[j] = (uint32_t)(arow[j] * 128) + SWZ(arow[j], acol[j]);
    }

    const int bstride = FT;
    int half = lane >> 4;
    int bn = half * 64 + (lane & 15) * 4;

    for (;;) {
        if (tid == 0) s_item = atomicAdd(&g_work1, 1);
        __syncthreads();
        int item = s_item;
        if (item >= total) break;

        int group = item / (nt * 8);
        int rem = item - group * nt * 8;
        int fb = group * 8 + (rem & 7);
        int tile = rem >> 3;
        int e = g_tile_e[tile];
        int row0 = g_tile_r0[tile];
        int f0 = fb * 64;

        const char* srcA[4];
#pragma unroll
        for (int j = 0; j < 4; j++) {
            int tok = g_perm[row0 + arow[j]];
            if (tok < 0) tok = 0;   // pad rows read token 0 (finite; output discarded)
            srcA[j] = (const char*)(g_xtok + (size_t)tok * DT + acol[j] * 8);
        }
        const float* srcB0 = ((half ? wi1 : wi0) + (size_t)e * DT * FT + f0 + (lane & 15) * 4)
                             + (size_t)(wid * 8) * FT;
        uint32_t bp[16];

        float cf[4][4][4];
#pragma unroll
        for (int a = 0; a < 4; a++)
#pragma unroll
            for (int b2 = 0; b2 < 4; b2++)
#pragma unroll
                for (int c = 0; c < 4; c++) cf[a][b2][c] = 0.f;

        GEMM_MAINLOOP(DT / BK);

        STORE_C_SMEM();
        __syncthreads();

        const float* Cs = (const float*)dynsm;
#pragma unroll
        for (int i = 0; i < 8; i++) {
            int pos = tid + i * 256;
            int m = pos >> 4;
            int f = (pos & 15) * 4;
            float hv[4];
#pragma unroll
            for (int u = 0; u < 4; u++) {
                float d0 = Cs[m * 132 + f + u];
                float d1 = Cs[m * 132 + 64 + f + u];
                hv[u] = (d0 / (1.0f + __expf(-d0))) * d1;
            }
            uint32_t p0 = packh2(hv[0], hv[1]);
            uint32_t p1 = packh2(hv[2], hv[3]);
            size_t o = (size_t)(row0 + m) * FT + f0 + f;
            *(uint2*)(g_hh + o) = make_uint2(p0, p1);
        }
        __syncthreads();
    }
}

// ---------------- launch 5: GEMM2 (persistent, atomic-free epilogue) ----------------
__global__ __launch_bounds__(256, 2) void gemm2_kernel(
        const float* __restrict__ wo) {
    extern __shared__ char dynsm[];
    __shared__ int s_item;
    int nt = g_ntiles;
    int total = nt * 8;
    int tid = threadIdx.x;
    int lane = tid & 31;
    int wid = tid >> 5;
    int wm = wid >> 2, wn = wid & 3;
    uint32_t sb = s2u(dynsm);

    uint32_t dstA[4];
    int arow[4], acol[4];
#pragma unroll
    for (int j = 0; j < 4; j++) {
        int id = tid + j * 256;
        arow[j] = (id >> 3) & 127;
        acol[j] = id & 7;
        dstA[j] = (uint32_t)(arow[j] * 128) + SWZ(arow[j], acol[j]);
    }

    const int bstride = DT;
    int bn = lane * 4;

    for (;;) {
        if (tid == 0) s_item = atomicAdd(&g_work2, 1);
        __syncthreads();
        int item = s_item;
        if (item >= total) break;

        int tile = item >> 3;
        int d0 = (item & 7) * 128;
        int e = g_tile_e[tile];
        int row0 = g_tile_r0[tile];

        const char* srcA[4];
#pragma unroll
        for (int j = 0; j < 4; j++)
            srcA[j] = (const char*)(g_hh + (size_t)(row0 + arow[j]) * FT + acol[j] * 8);
        const float* srcB0 = (wo + (size_t)e * FT * DT + d0 + lane * 4)
                             + (size_t)(wid * 8) * DT;
        uint32_t bp[16];

        float cf[4][4][4];
#pragma unroll
        for (int a = 0; a < 4; a++)
#pragma unroll
            for (int b2 = 0; b2 < 4; b2++)
#pragma unroll
                for (int c = 0; c < 4; c++) cf[a][b2][c] = 0.f;

        GEMM_MAINLOOP(FT / BK);

        STORE_C_SMEM();

        int* stok = (int*)(dynsm + 128 * 132 * 4);
        float* spw = (float*)(dynsm + 128 * 132 * 4 + 512);
        int* spk = (int*)(dynsm + 128 * 132 * 4 + 1024);
        if (tid < 128) {
            stok[tid] = g_perm[row0 + tid];
            spw[tid] = g_pw[row0 + tid];
            spk[tid] = g_pk[row0 + tid];
        }
        __syncthreads();

        const float* Cs = (const float*)dynsm;
#pragma unroll 8
        for (int i = 0; i < 64; i++) {
            int pos = tid + i * 256;
            int n = pos & 127, m = pos >> 7;
            int tok = stok[m];
            if (tok >= 0)
                g_cbuf[(size_t)spk[m] * TT * DT + (size_t)tok * DT + d0 + n]
                    = Cs[m * 132 + n] * spw[m];
        }
        __syncthreads();
    }
}

// ---------------- launch 6: combine  out = c0 + c1 ----------------
__global__ void combine_kernel(float* __restrict__ out) {
    size_t i = (size_t)blockIdx.x * blockDim.x + threadIdx.x;
    float4 a = ((const float4*)g_cbuf)[i];
    float4 b = ((const float4*)(g_cbuf + (size_t)TT * DT))[i];
    float4 r;
    r.x = a.x + b.x; r.y = a.y + b.y; r.z = a.z + b.z; r.w = a.w + b.w;
    ((float4*)out)[i] = r;
}

// ---------------- launch ----------------
extern "C" void kernel_launch(void* const* d_in, const int* in_sizes, int n_in,
                              void* d_out, int out_size) {
    const float* x   = (const float*)d_in[0];
    const float* gw  = (const float*)d_in[1];
    const float* wi0 = (const float*)d_in[2];
    const float* wi1 = (const float*)d_in[3];
    const float* wo  = (const float*)d_in[4];
    float* out = (float*)d_out;

    cudaFuncSetAttribute(gemm1_kernel, cudaFuncAttributeMaxDynamicSharedMemorySize, SMEM_SZ);
    cudaFuncSetAttribute(gemm2_kernel, cudaFuncAttributeMaxDynamicSharedMemorySize, SMEM_SZ);

    init_kernel<<<1, 32>>>();
    gate_conv_kernel<<<TT / 8, 256>>>(x, gw);
    plan_scatter_kernel<<<1, 256>>>();
    gemm1_kernel<<<296, 256, SMEM_SZ>>>(wi0, wi1);      // 4th launch -> ncu slot
    gemm2_kernel<<<296, 256, SMEM_SZ>>>(wo);
    combine_kernel<<<(TT * DT / 4) / 256, 256>>>(out);
}

// round 11
// speedup vs baseline: 1.0443x; 1.0443x over previous
#include <cuda_runtime.h>
#include <cuda_fp16.h>
#include <stdint.h>
#include <math.h>

// ---------------- problem constants ----------------
#define DT   1024
#define FT   4096
#define ET   8
#define TT   8192
#define KSEL 2

#define BM    128
#define SLOTS 17408
#define MAXT  136
#define BK    64

// ---- unified staging: A 16K | B 16K per stage, 3 stages ----
#define STG      32768
#define OFF_A    0
#define OFF_B    16384
#define SMEM_SZ  98304

// A swizzle: 16B chunk c (0..7) within 128B row r
#define SWZ(r, c) ((uint32_t)((((c) ^ ((r) & 7))) << 4))
// B swizzle: [K][N] rows of 256B (128 n x 2B)
#define BSWZ(k, n) ((uint32_t)((k) * 256 + (((((n) >> 3) ^ ((k) & 7))) << 4) + (((n) & 7) * 2)))

// ---------------- device scratch ----------------
__device__ unsigned short g_xah[(size_t)SLOTS * DT];   // fp16 x, slot order
__device__ unsigned short g_hh[(size_t)SLOTS * FT];    // fp16 h
__device__ unsigned short g_w0h[(size_t)ET * DT * FT]; // fp16 wi0
__device__ unsigned short g_w1h[(size_t)ET * DT * FT]; // fp16 wi1
__device__ unsigned short g_woh[(size_t)ET * FT * DT]; // fp16 wo
__device__ float g_cbuf[(size_t)2 * TT * DT];          // per-assignment-rank output

__device__ int   g_perm[SLOTS];
__device__ float g_pw[SLOTS];
__device__ unsigned char g_pk[SLOTS];
__device__ int   g_topk_e[TT * KSEL];
__device__ float g_topk_w[TT * KSEL];
__device__ int   g_counts[ET];
__device__ int   g_tile_e[MAXT];
__device__ int   g_tile_r0[MAXT];
__device__ int   g_ntiles;
__device__ int   g_work1;
__device__ int   g_work2;

// ---------------- helpers ----------------
__device__ __forceinline__ uint32_t s2u(const void* p) {
    uint32_t a;
    asm("{ .reg .u64 t; cvta.to.shared.u64 t, %1; cvt.u32.u64 %0, t; }" : "=r"(a) : "l"(p));
    return a;
}
__device__ __forceinline__ void cpasync16(uint32_t dst, const void* src) {
    asm volatile("cp.async.cg.shared.global [%0], [%1], 16;" :: "r"(dst), "l"(src));
}
#define CP_COMMIT() asm volatile("cp.async.commit_group;" ::: "memory")
#define CP_WAIT1()  asm volatile("cp.async.wait_group 1;" ::: "memory")
#define CP_WAIT0()  asm volatile("cp.async.wait_group 0;" ::: "memory")

__device__ __forceinline__ void ldsm4(uint32_t* r, uint32_t a) {
    asm volatile("ldmatrix.sync.aligned.m8n8.x4.shared.b16 {%0,%1,%2,%3}, [%4];"
                 : "=r"(r[0]), "=r"(r[1]), "=r"(r[2]), "=r"(r[3]) : "r"(a));
}
__device__ __forceinline__ void ldsm4t(uint32_t* r, uint32_t a) {
    asm volatile("ldmatrix.sync.aligned.m8n8.x4.trans.shared.b16 {%0,%1,%2,%3}, [%4];"
                 : "=r"(r[0]), "=r"(r[1]), "=r"(r[2]), "=r"(r[3]) : "r"(a));
}
__device__ __forceinline__ void mma16816(float* c, const uint32_t* a, const uint32_t* b) {
    asm volatile("mma.sync.aligned.m16n8k16.row.col.f32.f16.f16.f32 "
                 "{%0,%1,%2,%3}, {%4,%5,%6,%7}, {%8,%9}, {%0,%1,%2,%3};"
                 : "+f"(c[0]), "+f"(c[1]), "+f"(c[2]), "+f"(c[3])
                 : "r"(a[0]), "r"(a[1]), "r"(a[2]), "r"(a[3]), "r"(b[0]), "r"(b[1]));
}
__device__ __forceinline__ uint32_t packh2(float f0, float f1) {
    uint32_t d;
    asm("cvt.rn.f16x2.f32 %0, %1, %2;" : "=r"(d) : "f"(f1), "f"(f0));
    return d;
}

// ---------------- launch 1: init ----------------
__global__ void init_kernel() {
    int i = threadIdx.x;
    if (i < ET) g_counts[i] = 0;
    if (i == 8) g_work1 = 0;
    if (i == 9) g_work2 = 0;
}

// ---------------- launch 2: gating ----------------
__global__ void gate_kernel(const float* __restrict__ x, const float* __restrict__ gw) {
    int gwarp = (blockIdx.x * blockDim.x + threadIdx.x) >> 5;
    int lane = threadIdx.x & 31;
    if (gwarp >= TT) return;
    const float* xr = x + (size_t)gwarp * DT;
    float acc[ET];
#pragma unroll
    for (int e = 0; e < ET; e++) acc[e] = 0.f;
    for (int i = lane; i < DT; i += 32) {
        float xv = xr[i];
        const float* g = gw + (size_t)i * ET;
#pragma unroll
        for (int e = 0; e < ET; e++) acc[e] += xv * g[e];
    }
#pragma unroll
    for (int e = 0; e < ET; e++)
#pragma unroll
        for (int o = 16; o; o >>= 1)
            acc[e] += __shfl_xor_sync(0xFFFFFFFFu, acc[e], o);
    if (lane == 0) {
        int i0 = 0; float v0 = acc[0];
#pragma unroll
        for (int e = 1; e < ET; e++) if (acc[e] > v0) { v0 = acc[e]; i0 = e; }
        int i1 = -1; float v1 = -3.4e38f;
#pragma unroll
        for (int e = 0; e < ET; e++) if (e != i0 && acc[e] > v1) { v1 = acc[e]; i1 = e; }
        float e1 = expf(v1 - v0);
        float inv = 1.0f / (1.0f + e1);
        int b = gwarp * KSEL;
        g_topk_e[b] = i0;     g_topk_w[b] = inv;
        g_topk_e[b + 1] = i1; g_topk_w[b + 1] = e1 * inv;
        atomicAdd(&g_counts[i0], 1);
        atomicAdd(&g_counts[i1], 1);
    }
}

// ---------------- launch 3: plan + perm init + scatter (single block) ----------------
__global__ void plan_scatter_kernel() {
    __shared__ int s_padoff[ET];
    __shared__ int s_cur[ET];
    int tid = threadIdx.x;
    for (int i = tid; i < SLOTS; i += 256) g_perm[i] = -1;
    if (tid == 0) {
        int off = 0, tile = 0;
        for (int e = 0; e < ET; e++) {
            s_padoff[e] = off;
            int c = g_counts[e];
            int nt = (c + BM - 1) / BM;
            for (int t = 0; t < nt; t++) {
                g_tile_e[tile] = e;
                g_tile_r0[tile] = off + t * BM;
                tile++;
            }
            off += nt * BM;
        }
        g_ntiles = tile;
    }
    if (tid < ET) s_cur[tid] = 0;
    __syncthreads();
    for (int a = tid; a < TT * KSEL; a += 256) {
        int e = g_topk_e[a];
        int pos = atomicAdd(&s_cur[e], 1);
        int slot = s_padoff[e] + pos;
        g_perm[slot] = a >> 1;
        g_pw[slot] = g_topk_w[a];
        g_pk[slot] = (unsigned char)(a & 1);
    }
}

// ---------------- launch 4: gather-convert x + convert weights to fp16 ----------------
#define WBLK 4096   // blocks per weight tensor (8M float4 / 2048)
__global__ void convert_all_kernel(const float* __restrict__ x,
                                   const float* __restrict__ wi0,
                                   const float* __restrict__ wi1,
                                   const float* __restrict__ wo) {
    int bid = blockIdx.x, tid = threadIdx.x;
    if (bid < SLOTS) {
        int tok = g_perm[bid];
        float4 v = make_float4(0.f, 0.f, 0.f, 0.f);
        if (tok >= 0) v = ((const float4*)(x + (size_t)tok * DT))[tid];
        ((uint2*)g_xah)[(size_t)bid * (DT / 4) + tid] =
            make_uint2(packh2(v.x, v.y), packh2(v.z, v.w));
    } else {
        int gid = bid - SLOTS;
        int which = gid >> 12;
        int blk = gid & (WBLK - 1);
        const float* src = (which == 0) ? wi0 : (which == 1) ? wi1 : wo;
        unsigned short* dst = (which == 0) ? g_w0h : (which == 1) ? g_w1h : g_woh;
        size_t base = (size_t)blk * 2048 + tid;
#pragma unroll
        for (int it = 0; it < 8; it++) {
            size_t i = base + (size_t)it * 256;
            float4 v = ((const float4*)src)[i];
            ((uint2*)dst)[i] = make_uint2(packh2(v.x, v.y), packh2(v.z, v.w));
        }
    }
}

// ---------------- shared GEMM machinery (all-cp.async A+B) ----------------
#define ISSUE(s, KS) do {                                                \
    if ((s) < (KS)) {                                                    \
        uint32_t bb = sb + ((s) % 3) * STG;                              \
        _Pragma("unroll")                                                \
        for (int j = 0; j < 4; j++)                                      \
            cpasync16(bb + dstA[j], srcA[j] + (size_t)(s) * 128);        \
        _Pragma("unroll")                                                \
        for (int j = 0; j < 4; j++)                                      \
            cpasync16(bb + dstB[j], srcB[j] + (size_t)(s) * bkstep);     \
    }                                                                    \
    CP_COMMIT();                                                         \
} while (0)

#define GEMM_MAINLOOP(KS) do {                                           \
    ISSUE(0, KS);                                                        \
    ISSUE(1, KS);                                                        \
    for (int s = 0; s < (KS); s++) {                                     \
        CP_WAIT1();                                                      \
        __syncthreads();                                                 \
        ISSUE(s + 2, KS);                                                \
        uint32_t b = sb + (s % 3) * STG;                                 \
        _Pragma("unroll")                                                \
        for (int ks = 0; ks < 4; ks++) {                                 \
            uint32_t ah[4][4], bhf[4][2];                                \
            int rr = lane & 15;                                          \
            int ch = 2 * ks + (lane >> 4);                               \
            _Pragma("unroll")                                            \
            for (int mf = 0; mf < 4; mf++) {                             \
                int r = wm * 64 + mf * 16 + rr;                          \
                ldsm4(ah[mf], b + OFF_A + r * 128 + SWZ(r, ch));         \
            }                                                            \
            {                                                            \
                int mat = lane >> 3, li = lane & 7;                      \
                int kk = ks * 16 + ((mat & 1) << 3) + li;                \
                _Pragma("unroll")                                        \
                for (int bi = 0; bi < 2; bi++) {                         \
                    int nn = wn * 32 + bi * 16 + ((mat >> 1) << 3);      \
                    uint32_t t4[4];                                      \
                    ldsm4t(t4, b + OFF_B + BSWZ(kk, nn));                \
                    bhf[bi*2+0][0] = t4[0]; bhf[bi*2+0][1] = t4[1];      \
                    bhf[bi*2+1][0] = t4[2]; bhf[bi*2+1][1] = t4[3];      \
                }                                                        \
            }                                                            \
            _Pragma("unroll")                                            \
            for (int mf = 0; mf < 4; mf++)                               \
                _Pragma("unroll")                                        \
                for (int nf = 0; nf < 4; nf++)                           \
                    mma16816(cf[mf][nf], ah[mf], bhf[nf]);               \
        }                                                                \
    }                                                                    \
    CP_WAIT0();                                                          \
    __syncthreads();                                                     \
} while (0)

#define STORE_C_SMEM() do {                                              \
    float* Cs = (float*)dynsm;                                           \
    int g = lane >> 2, t4i = lane & 3;                                   \
    _Pragma("unroll")                                                    \
    for (int mf = 0; mf < 4; mf++)                                       \
        _Pragma("unroll")                                                \
        for (int nf = 0; nf < 4; nf++) {                                 \
            int m0 = wm * 64 + mf * 16 + g;                              \
            int n0 = wn * 32 + nf * 8 + 2 * t4i;                         \
            Cs[m0 * 132 + n0]           = cf[mf][nf][0];                 \
            Cs[m0 * 132 + n0 + 1]       = cf[mf][nf][1];                 \
            Cs[(m0 + 8) * 132 + n0]     = cf[mf][nf][2];                 \
            Cs[(m0 + 8) * 132 + n0 + 1] = cf[mf][nf][3];                 \
        }                                                                \
} while (0)

// ---------------- launch 5: GEMM1 (persistent) ----------------
__global__ __launch_bounds__(256, 2) void gemm1_kernel() {
    extern __shared__ char dynsm[];
    __shared__ int s_item;
    int nt = g_ntiles;
    int total = nt * 64;
    int tid = threadIdx.x;
    int lane = tid & 31;
    int wid = tid >> 5;
    int wm = wid >> 2, wn = wid & 3;
    uint32_t sb = s2u(dynsm);

    // A dst mapping: 1024 chunks (128 rows x 8), 4 per thread
    uint32_t dstA[4];
    int arow[4], acol[4];
#pragma unroll
    for (int j = 0; j < 4; j++) {
        int id = tid + j * 256;
        arow[j] = (id >> 3) & 127;
        acol[j] = id & 7;
        dstA[j] = (uint32_t)(arow[j] * 128) + SWZ(arow[j], acol[j]);
    }
    // B dst mapping: 1024 chunks (64 k-rows x 16), 4 per thread
    uint32_t dstB[4];
    int bk_[4], bc_[4];
#pragma unroll
    for (int j = 0; j < 4; j++) {
        int id = tid + j * 256;
        bk_[j] = id >> 4;
        bc_[j] = id & 15;
        dstB[j] = (uint32_t)(OFF_B + bk_[j] * 256 + (((bc_[j] ^ (bk_[j] & 7))) << 4));
    }
    const size_t bkstep = (size_t)64 * FT * sizeof(unsigned short);

    for (;;) {
        if (tid == 0) s_item = atomicAdd(&g_work1, 1);
        __syncthreads();
        int item = s_item;
        if (item >= total) break;

        int group = item / (nt * 8);
        int rem = item - group * nt * 8;
        int fb = group * 8 + (rem & 7);
        int tile = rem >> 3;
        int e = g_tile_e[tile];
        int row0 = g_tile_r0[tile];
        int f0 = fb * 64;

        const char* srcA[4];
#pragma unroll
        for (int j = 0; j < 4; j++)
            srcA[j] = (const char*)(g_xah + (size_t)(row0 + arow[j]) * DT + acol[j] * 8);
        const char* srcB[4];
#pragma unroll
        for (int j = 0; j < 4; j++) {
            const unsigned short* w = (bc_[j] < 8) ? g_w0h : g_w1h;
            int coff = (bc_[j] < 8) ? bc_[j] * 8 : (bc_[j] - 8) * 8;
            srcB[j] = (const char*)(w + (size_t)e * DT * FT
                                    + (size_t)bk_[j] * FT + f0 + coff);
        }

        float cf[4][4][4];
#pragma unroll
        for (int a = 0; a < 4; a++)
#pragma unroll
            for (int b2 = 0; b2 < 4; b2++)
#pragma unroll
                for (int c = 0; c < 4; c++) cf[a][b2][c] = 0.f;

        GEMM_MAINLOOP(DT / BK);

        STORE_C_SMEM();
        __syncthreads();

        const float* Cs = (const float*)dynsm;
#pragma unroll
        for (int i = 0; i < 8; i++) {
            int pos = tid + i * 256;
            int m = pos >> 4;
            int f = (pos & 15) * 4;
            float hv[4];
#pragma unroll
            for (int u = 0; u < 4; u++) {
                float d0 = Cs[m * 132 + f + u];
                float d1 = Cs[m * 132 + 64 + f + u];
                hv[u] = (d0 / (1.0f + __expf(-d0))) * d1;
            }
            uint32_t p0 = packh2(hv[0], hv[1]);
            uint32_t p1 = packh2(hv[2], hv[3]);
            size_t o = (size_t)(row0 + m) * FT + f0 + f;
            *(uint2*)(g_hh + o) = make_uint2(p0, p1);
        }
        __syncthreads();
    }
}

// ---------------- launch 6: GEMM2 (persistent, atomic-free epilogue) ----------------
__global__ __launch_bounds__(256, 2) void gemm2_kernel() {
    extern __shared__ char dynsm[];
    __shared__ int s_item;
    int nt = g_ntiles;
    int total = nt * 8;
    int tid = threadIdx.x;
    int lane = tid & 31;
    int wid = tid >> 5;
    int wm = wid >> 2, wn = wid & 3;
    uint32_t sb = s2u(dynsm);

    uint32_t dstA[4];
    int arow[4], acol[4];
#pragma unroll
    for (int j = 0; j < 4; j++) {
        int id = tid + j * 256;
        arow[j] = (id >> 3) & 127;
        acol[j] = id & 7;
        dstA[j] = (uint32_t)(arow[j] * 128) + SWZ(arow[j], acol[j]);
    }
    uint32_t dstB[4];
    int bk_[4], bc_[4];
#pragma unroll
    for (int j = 0; j < 4; j++) {
        int id = tid + j * 256;
        bk_[j] = id >> 4;
        bc_[j] = id & 15;
        dstB[j] = (uint32_t)(OFF_B + bk_[j] * 256 + (((bc_[j] ^ (bk_[j] & 7))) << 4));
    }
    const size_t bkstep = (size_t)64 * DT * sizeof(unsigned short);

    for (;;) {
        if (tid == 0) s_item = atomicAdd(&g_work2, 1);
        __syncthreads();
        int item = s_item;
        if (item >= total) break;

        int tile = item >> 3;
        int d0 = (item & 7) * 128;
        int e = g_tile_e[tile];
        int row0 = g_tile_r0[tile];

        const char* srcA[4];
#pragma unroll
        for (int j = 0; j < 4; j++)
            srcA[j] = (const char*)(g_hh + (size_t)(row0 + arow[j]) * FT + acol[j] * 8);
        const char* srcB[4];
#pragma unroll
        for (int j = 0; j < 4; j++)
            srcB[j] = (const char*)(g_woh + (size_t)e * FT * DT
                                    + (size_t)bk_[j] * DT + d0 + bc_[j] * 8);

        float cf[4][4][4];
#pragma unroll
        for (int a = 0; a < 4; a++)
#pragma unroll
            for (int b2 = 0; b2 < 4; b2++)
#pragma unroll
                for (int c = 0; c < 4; c++) cf[a][b2][c] = 0.f;

        GEMM_MAINLOOP(FT / BK);

        STORE_C_SMEM();

        int* stok = (int*)(dynsm + 128 * 132 * 4);
        float* spw = (float*)(dynsm + 128 * 132 * 4 + 512);
        int* spk = (int*)(dynsm + 128 * 132 * 4 + 1024);
        if (tid < 128) {
            stok[tid] = g_perm[row0 + tid];
            spw[tid] = g_pw[row0 + tid];
            spk[tid] = g_pk[row0 + tid];
        }
        __syncthreads();

        const float* Cs = (const float*)dynsm;
#pragma unroll 8
        for (int i = 0; i < 64; i++) {
            int pos = tid + i * 256;
            int n = pos & 127, m = pos >> 7;
            int tok = stok[m];
            if (tok >= 0)
                g_cbuf[(size_t)spk[m] * TT * DT + (size_t)tok * DT + d0 + n]
                    = Cs[m * 132 + n] * spw[m];
        }
        __syncthreads();
    }
}

// ---------------- launch 7: combine  out = c0 + c1 ----------------
__global__ void combine_kernel(float* __restrict__ out) {
    size_t i = (size_t)blockIdx.x * blockDim.x + threadIdx.x;
    float4 a = ((const float4*)g_cbuf)[i];
    float4 b = ((const float4*)(g_cbuf + (size_t)TT * DT))[i];
    float4 r;
    r.x = a.x + b.x; r.y = a.y + b.y; r.z = a.z + b.z; r.w = a.w + b.w;
    ((float4*)out)[i] = r;
}

// ---------------- launch ----------------
extern "C" void kernel_launch(void* const* d_in, const int* in_sizes, int n_in,
                              void* d_out, int out_size) {
    const float* x   = (const float*)d_in[0];
    const float* gw  = (const float*)d_in[1];
    const float* wi0 = (const float*)d_in[2];
    const float* wi1 = (const float*)d_in[3];
    const float* wo  = (const float*)d_in[4];
    float* out = (float*)d_out;

    cudaFuncSetAttribute(gemm1_kernel, cudaFuncAttributeMaxDynamicSharedMemorySize, SMEM_SZ);
    cudaFuncSetAttribute(gemm2_kernel, cudaFuncAttributeMaxDynamicSharedMemorySize, SMEM_SZ);

    init_kernel<<<1, 32>>>();
    gate_kernel<<<TT / 8, 256>>>(x, gw);
    plan_scatter_kernel<<<1, 256>>>();
    convert_all_kernel<<<SLOTS + 3 * WBLK, 256>>>(x, wi0, wi1, wo);
    gemm1_kernel<<<296, 256, SMEM_SZ>>>();
    gemm2_kernel<<<296, 256, SMEM_SZ>>>();
    combine_kernel<<<(TT * DT / 4) / 256, 256>>>(out);
}

// round 12
// speedup vs baseline: 1.0672x; 1.0220x over previous
#include <cuda_runtime.h>
#include <cuda_fp16.h>
#include <stdint.h>
#include <math.h>

// ---------------- problem constants ----------------
#define DT   1024
#define FT   4096
#define ET   8
#define TT   8192
#define KSEL 2

#define BM    128
#define SLOTS 17408
#define MAXT  136
#define BK    64

// ---- unified staging: A 16K | B 16K per stage, 3 stages ----
#define STG      32768
#define OFF_A    0
#define OFF_B    16384
#define SMEM_SZ  98304

// A swizzle: 16B chunk c (0..7) within 128B row r
#define SWZ(r, c) ((uint32_t)((((c) ^ ((r) & 7))) << 4))
// B swizzle: [K][N] rows of 256B (128 n x 2B)
#define BSWZ(k, n) ((uint32_t)((k) * 256 + (((((n) >> 3) ^ ((k) & 7))) << 4) + (((n) & 7) * 2)))

// ---------------- device scratch ----------------
__device__ unsigned short g_xah[(size_t)SLOTS * DT];   // fp16 x, slot order
__device__ unsigned short g_hh[(size_t)SLOTS * FT];    // fp16 h
__device__ unsigned short g_w0h[(size_t)ET * DT * FT]; // fp16 wi0
__device__ unsigned short g_w1h[(size_t)ET * DT * FT]; // fp16 wi1
__device__ unsigned short g_woh[(size_t)ET * FT * DT]; // fp16 wo
__device__ float g_cbuf[(size_t)2 * TT * DT];          // per-assignment-rank output

__device__ int   g_perm[SLOTS];
__device__ float g_pw[SLOTS];
__device__ unsigned char g_pk[SLOTS];
__device__ int   g_topk_e[TT * KSEL];
__device__ float g_topk_w[TT * KSEL];
__device__ int   g_counts[ET];
__device__ int   g_tile_e[MAXT];
__device__ int   g_tile_r0[MAXT];
__device__ int   g_ntiles;
__device__ int   g_work1;
__device__ int   g_work2;

// ---------------- helpers ----------------
__device__ __forceinline__ uint32_t s2u(const void* p) {
    uint32_t a;
    asm("{ .reg .u64 t; cvta.to.shared.u64 t, %1; cvt.u32.u64 %0, t; }" : "=r"(a) : "l"(p));
    return a;
}
__device__ __forceinline__ void cpasync16(uint32_t dst, const void* src) {
    asm volatile("cp.async.cg.shared.global [%0], [%1], 16;" :: "r"(dst), "l"(src));
}
#define CP_COMMIT() asm volatile("cp.async.commit_group;" ::: "memory")
#define CP_WAIT1()  asm volatile("cp.async.wait_group 1;" ::: "memory")
#define CP_WAIT0()  asm volatile("cp.async.wait_group 0;" ::: "memory")

__device__ __forceinline__ void ldsm4(uint32_t* r, uint32_t a) {
    asm volatile("ldmatrix.sync.aligned.m8n8.x4.shared.b16 {%0,%1,%2,%3}, [%4];"
                 : "=r"(r[0]), "=r"(r[1]), "=r"(r[2]), "=r"(r[3]) : "r"(a));
}
__device__ __forceinline__ void ldsm4t(uint32_t* r, uint32_t a) {
    asm volatile("ldmatrix.sync.aligned.m8n8.x4.trans.shared.b16 {%0,%1,%2,%3}, [%4];"
                 : "=r"(r[0]), "=r"(r[1]), "=r"(r[2]), "=r"(r[3]) : "r"(a));
}
__device__ __forceinline__ void mma16816(float* c, const uint32_t* a, const uint32_t* b) {
    asm volatile("mma.sync.aligned.m16n8k16.row.col.f32.f16.f16.f32 "
                 "{%0,%1,%2,%3}, {%4,%5,%6,%7}, {%8,%9}, {%0,%1,%2,%3};"
                 : "+f"(c[0]), "+f"(c[1]), "+f"(c[2]), "+f"(c[3])
                 : "r"(a[0]), "r"(a[1]), "r"(a[2]), "r"(a[3]), "r"(b[0]), "r"(b[1]));
}
__device__ __forceinline__ uint32_t packh2(float f0, float f1) {
    uint32_t d;
    asm("cvt.rn.f16x2.f32 %0, %1, %2;" : "=r"(d) : "f"(f1), "f"(f0));
    return d;
}

// ---------------- launch 1: init ----------------
__global__ void init_kernel() {
    int i = threadIdx.x;
    if (i < ET) g_counts[i] = 0;
    if (i == 8) g_work1 = 0;
    if (i == 9) g_work2 = 0;
}

// ---------------- launch 2: gating ----------------
__global__ void gate_kernel(const float* __restrict__ x, const float* __restrict__ gw) {
    int gwarp = (blockIdx.x * blockDim.x + threadIdx.x) >> 5;
    int lane = threadIdx.x & 31;
    if (gwarp >= TT) return;
    const float* xr = x + (size_t)gwarp * DT;
    float acc[ET];
#pragma unroll
    for (int e = 0; e < ET; e++) acc[e] = 0.f;
    for (int i = lane; i < DT; i += 32) {
        float xv = xr[i];
        const float* g = gw + (size_t)i * ET;
#pragma unroll
        for (int e = 0; e < ET; e++) acc[e] += xv * g[e];
    }
#pragma unroll
    for (int e = 0; e < ET; e++)
#pragma unroll
        for (int o = 16; o; o >>= 1)
            acc[e] += __shfl_xor_sync(0xFFFFFFFFu, acc[e], o);
    if (lane == 0) {
        int i0 = 0; float v0 = acc[0];
#pragma unroll
        for (int e = 1; e < ET; e++) if (acc[e] > v0) { v0 = acc[e]; i0 = e; }
        int i1 = -1; float v1 = -3.4e38f;
#pragma unroll
        for (int e = 0; e < ET; e++) if (e != i0 && acc[e] > v1) { v1 = acc[e]; i1 = e; }
        float e1 = expf(v1 - v0);
        float inv = 1.0f / (1.0f + e1);
        int b = gwarp * KSEL;
        g_topk_e[b] = i0;     g_topk_w[b] = inv;
        g_topk_e[b + 1] = i1; g_topk_w[b + 1] = e1 * inv;
        atomicAdd(&g_counts[i0], 1);
        atomicAdd(&g_counts[i1], 1);
    }
}

// ---------------- launch 3: plan + perm init + scatter ----------------
__global__ void plan_scatter_kernel() {
    __shared__ int s_padoff[ET];
    __shared__ int s_cur[ET];
    int tid = threadIdx.x;
    for (int i = tid; i < SLOTS; i += 256) g_perm[i] = -1;
    if (tid == 0) {
        int off = 0, tile = 0;
        for (int e = 0; e < ET; e++) {
            s_padoff[e] = off;
            int c = g_counts[e];
            int nt = (c + BM - 1) / BM;
            for (int t = 0; t < nt; t++) {
                g_tile_e[tile] = e;
                g_tile_r0[tile] = off + t * BM;
                tile++;
            }
            off += nt * BM;
        }
        g_ntiles = tile;
    }
    if (tid < ET) s_cur[tid] = 0;
    __syncthreads();
    for (int a = tid; a < TT * KSEL; a += 256) {
        int e = g_topk_e[a];
        int pos = atomicAdd(&s_cur[e], 1);
        int slot = s_padoff[e] + pos;
        g_perm[slot] = a >> 1;
        g_pw[slot] = g_topk_w[a];
        g_pk[slot] = (unsigned char)(a & 1);
    }
}

// ---------------- launch 4: gather-convert x + convert weights ----------------
#define WBLK 4096
__global__ void convert_all_kernel(const float* __restrict__ x,
                                   const float* __restrict__ wi0,
                                   const float* __restrict__ wi1,
                                   const float* __restrict__ wo) {
    int bid = blockIdx.x, tid = threadIdx.x;
    if (bid < SLOTS) {
        int tok = g_perm[bid];
        float4 v = make_float4(0.f, 0.f, 0.f, 0.f);
        if (tok >= 0) v = ((const float4*)(x + (size_t)tok * DT))[tid];
        ((uint2*)g_xah)[(size_t)bid * (DT / 4) + tid] =
            make_uint2(packh2(v.x, v.y), packh2(v.z, v.w));
    } else {
        int gid = bid - SLOTS;
        int which = gid >> 12;
        int blk = gid & (WBLK - 1);
        const float* src = (which == 0) ? wi0 : (which == 1) ? wi1 : wo;
        unsigned short* dst = (which == 0) ? g_w0h : (which == 1) ? g_w1h : g_woh;
        size_t base = (size_t)blk * 2048 + tid;
#pragma unroll
        for (int it = 0; it < 8; it++) {
            size_t i = base + (size_t)it * 256;
            float4 v = ((const float4*)src)[i];
            ((uint2*)dst)[i] = make_uint2(packh2(v.x, v.y), packh2(v.z, v.w));
        }
    }
}

// ---------------- shared GEMM machinery (128 threads, 64x64 warp tiles) ----------------
#define ISSUE(s, KS) do {                                                \
    if ((s) < (KS)) {                                                    \
        uint32_t bb = sb + ((s) % 3) * STG;                              \
        _Pragma("unroll")                                                \
        for (int j = 0; j < 8; j++)                                      \
            cpasync16(bb + dstA[j], srcA[j] + (size_t)(s) * 128);        \
        _Pragma("unroll")                                                \
        for (int j = 0; j < 8; j++)                                      \
            cpasync16(bb + dstB[j], srcB[j] + (size_t)(s) * bkstep);     \
    }                                                                    \
    CP_COMMIT();                                                         \
} while (0)

#define GEMM_MAINLOOP(KS) do {                                           \
    ISSUE(0, KS);                                                        \
    ISSUE(1, KS);                                                        \
    for (int s = 0; s < (KS); s++) {                                     \
        CP_WAIT1();                                                      \
        __syncthreads();                                                 \
        ISSUE(s + 2, KS);                                                \
        uint32_t b = sb + (s % 3) * STG;                                 \
        _Pragma("unroll")                                                \
        for (int ks = 0; ks < 4; ks++) {                                 \
            uint32_t ah[4][4], bhf[8][2];                                \
            int rr = lane & 15;                                          \
            int ch = 2 * ks + (lane >> 4);                               \
            _Pragma("unroll")                                            \
            for (int mf = 0; mf < 4; mf++) {                             \
                int r = wm * 64 + mf * 16 + rr;                          \
                ldsm4(ah[mf], b + OFF_A + r * 128 + SWZ(r, ch));         \
            }                                                            \
            {                                                            \
                int mat = lane >> 3, li = lane & 7;                      \
                int kk = ks * 16 + ((mat & 1) << 3) + li;                \
                _Pragma("unroll")                                        \
                for (int bi = 0; bi < 4; bi++) {                         \
                    int nn = wn * 64 + bi * 16 + ((mat >> 1) << 3);      \
                    uint32_t t4[4];                                      \
                    ldsm4t(t4, b + OFF_B + BSWZ(kk, nn));                \
                    bhf[bi*2+0][0] = t4[0]; bhf[bi*2+0][1] = t4[1];      \
                    bhf[bi*2+1][0] = t4[2]; bhf[bi*2+1][1] = t4[3];      \
                }                                                        \
            }                                                            \
            _Pragma("unroll")                                            \
            for (int mf = 0; mf < 4; mf++)                               \
                _Pragma("unroll")                                        \
                for (int nf = 0; nf < 8; nf++)                           \
                    mma16816(cf[mf][nf], ah[mf], bhf[nf]);               \
        }                                                                \
    }                                                                    \
    CP_WAIT0();                                                          \
    __syncthreads();                                                     \
} while (0)

#define STORE_C_SMEM() do {                                              \
    float* Cs = (float*)dynsm;                                           \
    int g = lane >> 2, t4i = lane & 3;                                   \
    _Pragma("unroll")                                                    \
    for (int mf = 0; mf < 4; mf++)                                       \
        _Pragma("unroll")                                                \
        for (int nf = 0; nf < 8; nf++) {                                 \
            int m0 = wm * 64 + mf * 16 + g;                              \
            int n0 = wn * 64 + nf * 8 + 2 * t4i;                         \
            Cs[m0 * 132 + n0]           = cf[mf][nf][0];                 \
            Cs[m0 * 132 + n0 + 1]       = cf[mf][nf][1];                 \
            Cs[(m0 + 8) * 132 + n0]     = cf[mf][nf][2];                 \
            Cs[(m0 + 8) * 132 + n0 + 1] = cf[mf][nf][3];                 \
        }                                                                \
} while (0)

// ---------------- launch 5: GEMM1 (persistent, 128 thr) ----------------
__global__ __launch_bounds__(128, 2) void gemm1_kernel() {
    extern __shared__ char dynsm[];
    __shared__ int s_item;
    int nt = g_ntiles;
    int total = nt * 64;
    int tid = threadIdx.x;
    int lane = tid & 31;
    int wid = tid >> 5;
    int wm = wid >> 1, wn = wid & 1;
    uint32_t sb = s2u(dynsm);

    uint32_t dstA[8];
    int arow[8], acol[8];
#pragma unroll
    for (int j = 0; j < 8; j++) {
        int id = tid + j * 128;
        arow[j] = (id >> 3) & 127;
        acol[j] = id & 7;
        dstA[j] = (uint32_t)(arow[j] * 128) + SWZ(arow[j], acol[j]);
    }
    uint32_t dstB[8];
    int bk_[8], bc_[8];
#pragma unroll
    for (int j = 0; j < 8; j++) {
        int id = tid + j * 128;
        bk_[j] = id >> 4;
        bc_[j] = id & 15;
        dstB[j] = (uint32_t)(OFF_B + bk_[j] * 256 + (((bc_[j] ^ (bk_[j] & 7))) << 4));
    }
    const size_t bkstep = (size_t)64 * FT * sizeof(unsigned short);

    for (;;) {
        if (tid == 0) s_item = atomicAdd(&g_work1, 1);
        __syncthreads();
        int item = s_item;
        if (item >= total) break;

        int group = item / (nt * 8);
        int rem = item - group * nt * 8;
        int fb = group * 8 + (rem & 7);
        int tile = rem >> 3;
        int e = g_tile_e[tile];
        int row0 = g_tile_r0[tile];
        int f0 = fb * 64;

        const char* srcA[8];
#pragma unroll
        for (int j = 0; j < 8; j++)
            srcA[j] = (const char*)(g_xah + (size_t)(row0 + arow[j]) * DT + acol[j] * 8);
        const char* srcB[8];
#pragma unroll
        for (int j = 0; j < 8; j++) {
            const unsigned short* w = (bc_[j] < 8) ? g_w0h : g_w1h;
            int coff = (bc_[j] < 8) ? bc_[j] * 8 : (bc_[j] - 8) * 8;
            srcB[j] = (const char*)(w + (size_t)e * DT * FT
                                    + (size_t)bk_[j] * FT + f0 + coff);
        }

        float cf[4][8][4];
#pragma unroll
        for (int a = 0; a < 4; a++)
#pragma unroll
            for (int b2 = 0; b2 < 8; b2++)
#pragma unroll
                for (int c = 0; c < 4; c++) cf[a][b2][c] = 0.f;

        GEMM_MAINLOOP(DT / BK);

        STORE_C_SMEM();
        __syncthreads();

        const float* Cs = (const float*)dynsm;
#pragma unroll
        for (int i = 0; i < 16; i++) {
            int pos = tid + i * 128;
            int m = pos >> 4;
            int f = (pos & 15) * 4;
            float hv[4];
#pragma unroll
            for (int u = 0; u < 4; u++) {
                float d0 = Cs[m * 132 + f + u];
                float d1 = Cs[m * 132 + 64 + f + u];
                hv[u] = (d0 / (1.0f + __expf(-d0))) * d1;
            }
            uint32_t p0 = packh2(hv[0], hv[1]);
            uint32_t p1 = packh2(hv[2], hv[3]);
            size_t o = (size_t)(row0 + m) * FT + f0 + f;
            *(uint2*)(g_hh + o) = make_uint2(p0, p1);
        }
        __syncthreads();
    }
}

// ---------------- launch 6: GEMM2 (persistent, 128 thr) ----------------
__global__ __launch_bounds__(128, 2) void gemm2_kernel() {
    extern __shared__ char dynsm[];
    __shared__ int s_item;
    int nt = g_ntiles;
    int total = nt * 8;
    int tid = threadIdx.x;
    int lane = tid & 31;
    int wid = tid >> 5;
    int wm = wid >> 1, wn = wid & 1;
    uint32_t sb = s2u(dynsm);

    uint32_t dstA[8];
    int arow[8], acol[8];
#pragma unroll
    for (int j = 0; j < 8; j++) {
        int id = tid + j * 128;
        arow[j] = (id >> 3) & 127;
        acol[j] = id & 7;
        dstA[j] = (uint32_t)(arow[j] * 128) + SWZ(arow[j], acol[j]);
    }
    uint32_t dstB[8];
    int bk_[8], bc_[8];
#pragma unroll
    for (int j = 0; j < 8; j++) {
        int id = tid + j * 128;
        bk_[j] = id >> 4;
        bc_[j] = id & 15;
        dstB[j] = (uint32_t)(OFF_B + bk_[j] * 256 + (((bc_[j] ^ (bk_[j] & 7))) << 4));
    }
    const size_t bkstep = (size_t)64 * DT * sizeof(unsigned short);

    for (;;) {
        if (tid == 0) s_item = atomicAdd(&g_work2, 1);
        __syncthreads();
        int item = s_item;
        if (item >= total) break;

        int tile = item >> 3;
        int d0 = (item & 7) * 128;
        int e = g_tile_e[tile];
        int row0 = g_tile_r0[tile];

        const char* srcA[8];
#pragma unroll
        for (int j = 0; j < 8; j++)
            srcA[j] = (const char*)(g_hh + (size_t)(row0 + arow[j]) * FT + acol[j] * 8);
        const char* srcB[8];
#pragma unroll
        for (int j = 0; j < 8; j++)
            srcB[j] = (const char*)(g_woh + (size_t)e * FT * DT
                                    + (size_t)bk_[j] * DT + d0 + bc_[j] * 8);

        float cf[4][8][4];
#pragma unroll
        for (int a = 0; a < 4; a++)
#pragma unroll
            for (int b2 = 0; b2 < 8; b2++)
#pragma unroll
                for (int c = 0; c < 4; c++) cf[a][b2][c] = 0.f;

        GEMM_MAINLOOP(FT / BK);

        STORE_C_SMEM();

        int* stok = (int*)(dynsm + 128 * 132 * 4);
        float* spw = (float*)(dynsm + 128 * 132 * 4 + 512);
        int* spk = (int*)(dynsm + 128 * 132 * 4 + 1024);
        if (tid < 128) {
            stok[tid] = g_perm[row0 + tid];
            spw[tid] = g_pw[row0 + tid];
            spk[tid] = g_pk[row0 + tid];
        }
        __syncthreads();

        const float* Cs = (const float*)dynsm;
#pragma unroll 8
        for (int i = 0; i < 128; i++) {
            int pos = tid + i * 128;
            int n = pos & 127, m = pos >> 7;
            int tok = stok[m];
            if (tok >= 0)
                g_cbuf[(size_t)spk[m] * TT * DT + (size_t)tok * DT + d0 + n]
                    = Cs[m * 132 + n] * spw[m];
        }
        __syncthreads();
    }
}

// ---------------- launch 7: combine ----------------
__global__ void combine_kernel(float* __restrict__ out) {
    size_t i = (size_t)blockIdx.x * blockDim.x + threadIdx.x;
    float4 a = ((const float4*)g_cbuf)[i];
    float4 b = ((const float4*)(g_cbuf + (size_t)TT * DT))[i];
    float4 r;
    r.x = a.x + b.x; r.y = a.y + b.y; r.z = a.z + b.z; r.w = a.w + b.w;
    ((float4*)out)[i] = r;
}

// ---------------- launch ----------------
extern "C" void kernel_launch(void* const* d_in, const int* in_sizes, int n_in,
                              void* d_out, int out_size) {
    const float* x   = (const float*)d_in[0];
    const float* gw  = (const float*)d_in[1];
    const float* wi0 = (const float*)d_in[2];
    const float* wi1 = (const float*)d_in[3];
    const float* wo  = (const float*)d_in[4];
    float* out = (float*)d_out;

    cudaFuncSetAttribute(gemm1_kernel, cudaFuncAttributeMaxDynamicSharedMemorySize, SMEM_SZ);
    cudaFuncSetAttribute(gemm2_kernel, cudaFuncAttributeMaxDynamicSharedMemorySize, SMEM_SZ);

    init_kernel<<<1, 32>>>();
    gate_kernel<<<TT / 8, 256>>>(x, gw);
    plan_scatter_kernel<<<1, 256>>>();
    convert_all_kernel<<<SLOTS + 3 * WBLK, 256>>>(x, wi0, wi1, wo);
    gemm1_kernel<<<296, 128, SMEM_SZ>>>();
    gemm2_kernel<<<296, 128, SMEM_SZ>>>();
    combine_kernel<<<(TT * DT / 4) / 256, 256>>>(out);
}